// round 1
// baseline (speedup 1.0000x reference)
#include <cuda_runtime.h>
#include <cuda_bf16.h>
#include <math.h>

#define NMAX 100000
#define EMAX 1600000

// ---------------- device scratch (static, allowed) ----------------
__device__ float g_dinv[NMAX];
__device__ int   g_cnt[NMAX];
__device__ int   g_fill[NMAX];
__device__ int   g_rowptr[NMAX + 1];
__device__ int   g_col[EMAX];
__device__ float g_bufA[(size_t)NMAX * 128];
__device__ float g_bufB[(size_t)NMAX * 128];
__device__ float g_h2[(size_t)NMAX * 128];

// ---------------- CSR build ----------------
__global__ void zero_counts_kernel(int n) {
    int i = blockIdx.x * blockDim.x + threadIdx.x;
    if (i < n) { g_cnt[i] = 0; g_fill[i] = 0; }
}

__global__ void count_edges_kernel(const int* __restrict__ dst, int e) {
    int i = blockIdx.x * blockDim.x + threadIdx.x;
    if (i < e) atomicAdd(&g_cnt[dst[i]], 1);
}

__global__ void dinv_kernel(int n) {
    int i = blockIdx.x * blockDim.x + threadIdx.x;
    if (i < n) g_dinv[i] = rsqrtf((float)(g_cnt[i] + 1));  // +1 self loop
}

// single-block exclusive scan of g_cnt -> g_rowptr
__global__ void scan_kernel(int n) {
    __shared__ int s[1024];
    int tid = threadIdx.x;
    int carry = 0;
    for (int base = 0; base < n; base += 1024) {
        int i = base + tid;
        int v = (i < n) ? g_cnt[i] : 0;
        s[tid] = v;
        __syncthreads();
        for (int off = 1; off < 1024; off <<= 1) {
            int t2 = (tid >= off) ? s[tid - off] : 0;
            __syncthreads();
            s[tid] += t2;
            __syncthreads();
        }
        int incl = s[tid];
        if (i < n) g_rowptr[i] = carry + incl - v;
        int tot = s[1023];
        __syncthreads();
        carry += tot;
    }
    if (tid == 0) g_rowptr[n] = carry;
}

__global__ void scatter_edges_kernel(const int* __restrict__ src,
                                     const int* __restrict__ dst, int e) {
    int i = blockIdx.x * blockDim.x + threadIdx.x;
    if (i < e) {
        int d = dst[i];
        int p = g_rowptr[d] + atomicAdd(&g_fill[d], 1);
        g_col[p] = src[i];
    }
}

// ---------------- GEMM with output row-scaling by dinv ----------------
// out[v][c] = dinv[v] * sum_k A[v][k] * W[k][c]
template <int K, int C>
__global__ __launch_bounds__(256) void gemm_scale_kernel(
    const float* __restrict__ A, const float* __restrict__ W,
    float* __restrict__ out, int n) {
    constexpr int ROWS = 32;
    constexpr int CG = C / 4;                 // col-groups of 4
    constexpr int RPT = ROWS * C / (256 * 4); // rows per thread
    extern __shared__ float sm[];
    float* Ws = sm;              // K*C
    float* As = sm + K * C;      // ROWS*K
    int t = threadIdx.x;
    int row0 = blockIdx.x * ROWS;

    for (int i = t; i < K * C / 4; i += 256)
        ((float4*)Ws)[i] = ((const float4*)W)[i];
    for (int i = t; i < ROWS * K / 4; i += 256) {
        int r = (i * 4) / K;
        int k = (i * 4) % K;
        int gr = row0 + r;
        float4 v = make_float4(0.f, 0.f, 0.f, 0.f);
        if (gr < n) v = *(const float4*)(A + (size_t)gr * K + k);
        *(float4*)&As[r * K + k] = v;
    }
    __syncthreads();

    int tc = (t % CG) * 4;
    int tr = (t / CG) * RPT;
    float4 acc[RPT];
#pragma unroll
    for (int r = 0; r < RPT; r++) acc[r] = make_float4(0.f, 0.f, 0.f, 0.f);

    for (int k = 0; k < K; k += 4) {
        float4 wv0 = *(float4*)&Ws[(k + 0) * C + tc];
        float4 wv1 = *(float4*)&Ws[(k + 1) * C + tc];
        float4 wv2 = *(float4*)&Ws[(k + 2) * C + tc];
        float4 wv3 = *(float4*)&Ws[(k + 3) * C + tc];
#pragma unroll
        for (int r = 0; r < RPT; r++) {
            float4 a4 = *(float4*)&As[(tr + r) * K + k];
            acc[r].x += a4.x * wv0.x + a4.y * wv1.x + a4.z * wv2.x + a4.w * wv3.x;
            acc[r].y += a4.x * wv0.y + a4.y * wv1.y + a4.z * wv2.y + a4.w * wv3.y;
            acc[r].z += a4.x * wv0.z + a4.y * wv1.z + a4.z * wv2.z + a4.w * wv3.z;
            acc[r].w += a4.x * wv0.w + a4.y * wv1.w + a4.z * wv2.w + a4.w * wv3.w;
        }
    }
#pragma unroll
    for (int r = 0; r < RPT; r++) {
        int gr = row0 + tr + r;
        if (gr < n) {
            float s = g_dinv[gr];
            float4 v;
            v.x = s * acc[r].x; v.y = s * acc[r].y;
            v.z = s * acc[r].z; v.w = s * acc[r].w;
            *(float4*)(out + (size_t)gr * C + tc) = v;
        }
    }
}

// ---------------- aggregation: out[v] = dinv[v]*(sum_nbr hs[u] + hs[v]) + b ----------------
template <int D, bool RELU>
__global__ __launch_bounds__(256) void agg_kernel(
    const float* __restrict__ hs, const float* __restrict__ bias,
    float* __restrict__ out, int n) {
    constexpr int LPN = D / 4;  // lanes per node
    int idx = blockIdx.x * blockDim.x + threadIdx.x;
    int v = idx / LPN;
    int lane = idx % LPN;
    if (v >= n) return;
    int c = lane * 4;
    const float4* base = (const float4*)hs;
    size_t self = ((size_t)v * D + c) >> 2;
    float4 acc = base[self];  // self loop
    float4 acc2 = make_float4(0.f, 0.f, 0.f, 0.f);
    int beg = g_rowptr[v], end = g_rowptr[v + 1];
    int e = beg;
    for (; e + 1 < end; e += 2) {
        int u0 = g_col[e], u1 = g_col[e + 1];
        float4 m0 = base[((size_t)u0 * D + c) >> 2];
        float4 m1 = base[((size_t)u1 * D + c) >> 2];
        acc.x += m0.x; acc.y += m0.y; acc.z += m0.z; acc.w += m0.w;
        acc2.x += m1.x; acc2.y += m1.y; acc2.z += m1.z; acc2.w += m1.w;
    }
    if (e < end) {
        int u = g_col[e];
        float4 m = base[((size_t)u * D + c) >> 2];
        acc.x += m.x; acc.y += m.y; acc.z += m.z; acc.w += m.w;
    }
    acc.x += acc2.x; acc.y += acc2.y; acc.z += acc2.z; acc.w += acc2.w;
    float s = g_dinv[v];
    float4 b = *(const float4*)(bias + c);
    float4 r;
    r.x = s * acc.x + b.x; r.y = s * acc.y + b.y;
    r.z = s * acc.z + b.z; r.w = s * acc.w + b.w;
    if (RELU) {
        r.x = fmaxf(r.x, 0.f); r.y = fmaxf(r.y, 0.f);
        r.z = fmaxf(r.z, 0.f); r.w = fmaxf(r.w, 0.f);
    }
    ((float4*)out)[self] = r;
}

// ---------------- final: sigmoid(concat(h2, xl) @ Wf + bf) ----------------
__global__ __launch_bounds__(256) void final_kernel(
    const float* __restrict__ H, const float* __restrict__ L,
    const float* __restrict__ Wf, const float* __restrict__ bf,
    float* __restrict__ out, int n) {
    constexpr int KT = 192, C = 64, ROWS = 32;
    extern __shared__ float sm[];
    float* Ws = sm;                 // 192*64
    float* As = sm + KT * C;        // 32*192
    int t = threadIdx.x;
    int row0 = blockIdx.x * ROWS;

    for (int i = t; i < KT * C / 4; i += 256)
        ((float4*)Ws)[i] = ((const float4*)Wf)[i];
    for (int i = t; i < ROWS * 128 / 4; i += 256) {
        int r = (i * 4) / 128, k = (i * 4) % 128;
        int gr = row0 + r;
        float4 v = make_float4(0.f, 0.f, 0.f, 0.f);
        if (gr < n) v = *(const float4*)(H + (size_t)gr * 128 + k);
        *(float4*)&As[r * KT + k] = v;
    }
    for (int i = t; i < ROWS * 64 / 4; i += 256) {
        int r = (i * 4) / 64, k = (i * 4) % 64;
        int gr = row0 + r;
        float4 v = make_float4(0.f, 0.f, 0.f, 0.f);
        if (gr < n) v = *(const float4*)(L + (size_t)gr * 64 + k);
        *(float4*)&As[r * KT + 128 + k] = v;
    }
    __syncthreads();

    int tc = (t & 15) * 4;
    int tr = (t >> 4) * 2;
    float4 acc[2];
    acc[0] = make_float4(0.f, 0.f, 0.f, 0.f);
    acc[1] = make_float4(0.f, 0.f, 0.f, 0.f);
    for (int k = 0; k < KT; k += 4) {
        float4 wv0 = *(float4*)&Ws[(k + 0) * C + tc];
        float4 wv1 = *(float4*)&Ws[(k + 1) * C + tc];
        float4 wv2 = *(float4*)&Ws[(k + 2) * C + tc];
        float4 wv3 = *(float4*)&Ws[(k + 3) * C + tc];
#pragma unroll
        for (int r = 0; r < 2; r++) {
            float4 a4 = *(float4*)&As[(tr + r) * KT + k];
            acc[r].x += a4.x * wv0.x + a4.y * wv1.x + a4.z * wv2.x + a4.w * wv3.x;
            acc[r].y += a4.x * wv0.y + a4.y * wv1.y + a4.z * wv2.y + a4.w * wv3.y;
            acc[r].z += a4.x * wv0.z + a4.y * wv1.z + a4.z * wv2.z + a4.w * wv3.z;
            acc[r].w += a4.x * wv0.w + a4.y * wv1.w + a4.z * wv2.w + a4.w * wv3.w;
        }
    }
#pragma unroll
    for (int r = 0; r < 2; r++) {
        int gr = row0 + tr + r;
        if (gr < n) {
            float4 b = *(const float4*)(bf + tc);
            float4 z;
            z.x = 1.f / (1.f + expf(-(acc[r].x + b.x)));
            z.y = 1.f / (1.f + expf(-(acc[r].y + b.y)));
            z.z = 1.f / (1.f + expf(-(acc[r].z + b.z)));
            z.w = 1.f / (1.f + expf(-(acc[r].w + b.w)));
            *(float4*)(out + (size_t)gr * 64 + tc) = z;
        }
    }
}

// ---------------- host launch ----------------
extern "C" void kernel_launch(void* const* d_in, const int* in_sizes, int n_in,
                              void* d_out, int out_size) {
    const float* x   = (const float*)d_in[0];
    const float* y   = (const float*)d_in[1];
    const int*   ei  = (const int*)d_in[2];
    const float* Wg1 = (const float*)d_in[3];
    const float* bg1 = (const float*)d_in[4];
    const float* Wg2 = (const float*)d_in[5];
    const float* bg2 = (const float*)d_in[6];
    const float* Wl  = (const float*)d_in[7];
    const float* bl  = (const float*)d_in[8];
    const float* Wf  = (const float*)d_in[9];
    const float* bf  = (const float*)d_in[10];
    float* out = (float*)d_out;

    int n = in_sizes[0] / 128;
    int e = in_sizes[2] / 2;
    const int* src = ei;
    const int* dst = ei + e;

    float *bufA, *bufB, *h2;
    cudaGetSymbolAddress((void**)&bufA, g_bufA);
    cudaGetSymbolAddress((void**)&bufB, g_bufB);
    cudaGetSymbolAddress((void**)&h2, g_h2);

    cudaFuncSetAttribute(gemm_scale_kernel<128, 128>,
                         cudaFuncAttributeMaxDynamicSharedMemorySize,
                         (128 * 128 + 32 * 128) * 4);
    cudaFuncSetAttribute(final_kernel,
                         cudaFuncAttributeMaxDynamicSharedMemorySize,
                         (192 * 64 + 32 * 192) * 4);

    int nb_n = (n + 255) / 256;
    int nb_e = (e + 255) / 256;

    // CSR + dinv
    zero_counts_kernel<<<nb_n, 256>>>(n);
    count_edges_kernel<<<nb_e, 256>>>(dst, e);
    dinv_kernel<<<nb_n, 256>>>(n);
    scan_kernel<<<1, 1024>>>(n);
    scatter_edges_kernel<<<nb_e, 256>>>(src, dst, e);

    int gemm_blocks = (n + 31) / 32;
    size_t smem128 = (size_t)(128 * 128 + 32 * 128) * 4;
    size_t smem64  = (size_t)(64 * 64 + 32 * 64) * 4;
    size_t smemF   = (size_t)(192 * 64 + 32 * 192) * 4;
    int agg128_blocks = (int)(((size_t)n * 32 + 255) / 256);
    int agg64_blocks  = (int)(((size_t)n * 16 + 255) / 256);

    // feature branch
    gemm_scale_kernel<128, 128><<<gemm_blocks, 256, smem128>>>(x, Wg1, bufA, n);
    agg_kernel<128, true><<<agg128_blocks, 256>>>(bufA, bg1, bufB, n);
    gemm_scale_kernel<128, 128><<<gemm_blocks, 256, smem128>>>(bufB, Wg2, bufA, n);
    agg_kernel<128, false><<<agg128_blocks, 256>>>(bufA, bg2, h2, n);

    // label branch (10 layers, relu except last); result ends in bufB
    gemm_scale_kernel<64, 64><<<gemm_blocks, 256, smem64>>>(y, Wl, bufA, n);
    agg_kernel<64, true><<<agg64_blocks, 256>>>(bufA, bl, bufB, n);
    for (int j = 1; j < 10; j++) {
        gemm_scale_kernel<64, 64><<<gemm_blocks, 256, smem64>>>(
            bufB, Wl + (size_t)j * 64 * 64, bufA, n);
        if (j < 9)
            agg_kernel<64, true><<<agg64_blocks, 256>>>(bufA, bl + (size_t)j * 64, bufB, n);
        else
            agg_kernel<64, false><<<agg64_blocks, 256>>>(bufA, bl + (size_t)j * 64, bufB, n);
    }

    // final fused layer
    final_kernel<<<gemm_blocks, 256, smemF>>>(h2, bufB, Wf, bf, out, n);
}

// round 2
// speedup vs baseline: 1.1850x; 1.1850x over previous
#include <cuda_runtime.h>
#include <cuda_bf16.h>
#include <math.h>

#define NMAX 100000
#define EMAX 1600000

// ---------------- device scratch ----------------
__device__ float g_dinv[NMAX];
__device__ int   g_cnt[NMAX];
__device__ int   g_fill[NMAX];
__device__ int   g_rowptr[NMAX + 1];
__device__ int   g_bsum[256];
__device__ int   g_col[EMAX];
__device__ float g_bufA[(size_t)NMAX * 128];
__device__ float g_bufB[(size_t)NMAX * 128];
__device__ float g_h2[(size_t)NMAX * 128];

// ---------------- CSR build ----------------
__global__ void zero_counts_kernel(int n) {
    int i = blockIdx.x * blockDim.x + threadIdx.x;
    if (i < n) { g_cnt[i] = 0; g_fill[i] = 0; }
}

__global__ void count_edges_kernel(const int* __restrict__ dst, int e) {
    int i = blockIdx.x * blockDim.x + threadIdx.x;
    if (i < e) atomicAdd(&g_cnt[dst[i]], 1);
}

// pass 1: per-block exclusive scan of g_cnt into g_rowptr (local), block sums
// to g_bsum, and dinv computed on the fly.
__global__ void scan1_kernel(int n) {
    __shared__ int s[1024];
    int tid = threadIdx.x;
    int i = blockIdx.x * 1024 + tid;
    int v = (i < n) ? g_cnt[i] : 0;
    s[tid] = v;
    __syncthreads();
    for (int off = 1; off < 1024; off <<= 1) {
        int t2 = (tid >= off) ? s[tid - off] : 0;
        __syncthreads();
        s[tid] += t2;
        __syncthreads();
    }
    if (i < n) {
        g_rowptr[i] = s[tid] - v;               // local exclusive
        g_dinv[i] = rsqrtf((float)(v + 1));     // +1 self loop
    }
    if (tid == 1023) g_bsum[blockIdx.x] = s[1023];
}

// pass 2: scan the (<=128) block sums in one small block
__global__ void scan2_kernel(int nb) {
    __shared__ int s[128];
    int tid = threadIdx.x;
    int v = (tid < nb) ? g_bsum[tid] : 0;
    s[tid] = v;
    __syncthreads();
    for (int off = 1; off < 128; off <<= 1) {
        int t2 = (tid >= off) ? s[tid - off] : 0;
        __syncthreads();
        s[tid] += t2;
        __syncthreads();
    }
    if (tid < nb) g_bsum[tid] = s[tid] - v;     // exclusive
    if (tid == 127) g_bsum[nb] = s[127];        // total
}

// pass 3: add block offsets; set rowptr[n]
__global__ void scan3_kernel(int n, int nb) {
    int i = blockIdx.x * blockDim.x + threadIdx.x;
    if (i < n) g_rowptr[i] += g_bsum[i >> 10];
    if (i == 0) g_rowptr[n] = g_bsum[nb];
}

__global__ void scatter_edges_kernel(const int* __restrict__ src,
                                     const int* __restrict__ dst, int e) {
    int i = blockIdx.x * blockDim.x + threadIdx.x;
    if (i < e) {
        int d = dst[i];
        int p = g_rowptr[d] + atomicAdd(&g_fill[d], 1);
        g_col[p] = src[i];
    }
}

// ---------------- register-tiled GEMM ----------------
// Computes out[v][c0:c0+64] for a BM=128 row tile.
// A is split into two sources: rows come from A1 (width K1) for k<K1 and
// A2 (width K-K1) for k>=K1 (used by the final concat GEMM; else K1==K).
// EPI 0: out = dinv[v] * acc                (pre-aggregation product)
// EPI 1: out = sigmoid(acc + bias[c])      (final layer)
#define BM 128
#define BN 64
#define BK 64
#define KCP (BK + 8)

template <int K, int C, int K1, int EPI>
__global__ __launch_bounds__(128) void gemm_kernel(
    const float* __restrict__ A1, const float* __restrict__ A2,
    const float* __restrict__ W, const float* __restrict__ bias,
    float* __restrict__ out, int n) {
    extern __shared__ float sm[];
    float* Ws = sm;               // K * BN
    float* As = sm + K * BN;      // BM * KCP
    const int t = threadIdx.x;
    const int row0 = blockIdx.x * BM;
    const int bn0 = blockIdx.y * BN;

    // load W tile [K][BN]
    for (int idx = t; idx < K * BN / 4; idx += 128) {
        int k = idx / (BN / 4);
        int j = (idx % (BN / 4)) * 4;
        *(float4*)&Ws[k * BN + j] = *(const float4*)(W + (size_t)k * C + bn0 + j);
    }

    const int tc = (t % 8) * 8;
    const int tr = (t / 8) * 8;
    float4 acc[8][2];
#pragma unroll
    for (int i = 0; i < 8; i++) {
        acc[i][0] = make_float4(0.f, 0.f, 0.f, 0.f);
        acc[i][1] = make_float4(0.f, 0.f, 0.f, 0.f);
    }

    for (int c0 = 0; c0 < K; c0 += BK) {
        __syncthreads();
        // load A chunk [BM][BK] row-major, padded stride
#pragma unroll
        for (int p = 0; p < BM * BK / 4 / 128; p++) {
            int idx = t + p * 128;
            int r = idx / (BK / 4);
            int kq = (idx % (BK / 4)) * 4;
            int gr = row0 + r;
            float4 v = make_float4(0.f, 0.f, 0.f, 0.f);
            if (gr < n) {
                if (c0 < K1)
                    v = *(const float4*)(A1 + (size_t)gr * K1 + c0 + kq);
                else
                    v = *(const float4*)(A2 + (size_t)gr * (K - K1) + (c0 - K1) + kq);
            }
            *(float4*)&As[r * KCP + kq] = v;
        }
        __syncthreads();

#pragma unroll 4
        for (int k = 0; k < BK; k++) {
            int kk = c0 + k;
            float4 w0 = *(float4*)&Ws[kk * BN + tc];
            float4 w1 = *(float4*)&Ws[kk * BN + tc + 4];
            float a[8];
#pragma unroll
            for (int i = 0; i < 8; i++) a[i] = As[(tr + i) * KCP + k];
#pragma unroll
            for (int i = 0; i < 8; i++) {
                acc[i][0].x += a[i] * w0.x; acc[i][0].y += a[i] * w0.y;
                acc[i][0].z += a[i] * w0.z; acc[i][0].w += a[i] * w0.w;
                acc[i][1].x += a[i] * w1.x; acc[i][1].y += a[i] * w1.y;
                acc[i][1].z += a[i] * w1.z; acc[i][1].w += a[i] * w1.w;
            }
        }
    }

#pragma unroll
    for (int i = 0; i < 8; i++) {
        int gr = row0 + tr + i;
        if (gr >= n) continue;
        float4 v0 = acc[i][0], v1 = acc[i][1];
        if (EPI == 0) {
            float s = g_dinv[gr];
            v0.x *= s; v0.y *= s; v0.z *= s; v0.w *= s;
            v1.x *= s; v1.y *= s; v1.z *= s; v1.w *= s;
        } else {
            float4 b0 = *(const float4*)(bias + bn0 + tc);
            float4 b1 = *(const float4*)(bias + bn0 + tc + 4);
            v0.x = 1.f / (1.f + expf(-(v0.x + b0.x)));
            v0.y = 1.f / (1.f + expf(-(v0.y + b0.y)));
            v0.z = 1.f / (1.f + expf(-(v0.z + b0.z)));
            v0.w = 1.f / (1.f + expf(-(v0.w + b0.w)));
            v1.x = 1.f / (1.f + expf(-(v1.x + b1.x)));
            v1.y = 1.f / (1.f + expf(-(v1.y + b1.y)));
            v1.z = 1.f / (1.f + expf(-(v1.z + b1.z)));
            v1.w = 1.f / (1.f + expf(-(v1.w + b1.w)));
        }
        *(float4*)(out + (size_t)gr * C + bn0 + tc) = v0;
        *(float4*)(out + (size_t)gr * C + bn0 + tc + 4) = v1;
    }
}

// ---------------- aggregation: out[v] = dinv[v]*(sum_nbr hs[u] + hs[v]) + b ----------------
template <int D, bool RELU>
__global__ __launch_bounds__(256) void agg_kernel(
    const float* __restrict__ hs, const float* __restrict__ bias,
    float* __restrict__ out, int n) {
    constexpr int LPN = D / 4;
    int idx = blockIdx.x * blockDim.x + threadIdx.x;
    int v = idx / LPN;
    int lane = idx % LPN;
    if (v >= n) return;
    int c = lane * 4;
    const float4* base = (const float4*)hs;
    size_t self = ((size_t)v * D + c) >> 2;
    float4 acc = base[self];  // self loop
    float4 acc2 = make_float4(0.f, 0.f, 0.f, 0.f);
    int beg = g_rowptr[v], end = g_rowptr[v + 1];
    int e = beg;
    for (; e + 1 < end; e += 2) {
        int u0 = g_col[e], u1 = g_col[e + 1];
        float4 m0 = base[((size_t)u0 * D + c) >> 2];
        float4 m1 = base[((size_t)u1 * D + c) >> 2];
        acc.x += m0.x; acc.y += m0.y; acc.z += m0.z; acc.w += m0.w;
        acc2.x += m1.x; acc2.y += m1.y; acc2.z += m1.z; acc2.w += m1.w;
    }
    if (e < end) {
        int u = g_col[e];
        float4 m = base[((size_t)u * D + c) >> 2];
        acc.x += m.x; acc.y += m.y; acc.z += m.z; acc.w += m.w;
    }
    acc.x += acc2.x; acc.y += acc2.y; acc.z += acc2.z; acc.w += acc2.w;
    float s = g_dinv[v];
    float4 b = *(const float4*)(bias + c);
    float4 r;
    r.x = s * acc.x + b.x; r.y = s * acc.y + b.y;
    r.z = s * acc.z + b.z; r.w = s * acc.w + b.w;
    if (RELU) {
        r.x = fmaxf(r.x, 0.f); r.y = fmaxf(r.y, 0.f);
        r.z = fmaxf(r.z, 0.f); r.w = fmaxf(r.w, 0.f);
    }
    ((float4*)out)[self] = r;
}

// ---------------- host launch ----------------
extern "C" void kernel_launch(void* const* d_in, const int* in_sizes, int n_in,
                              void* d_out, int out_size) {
    const float* x   = (const float*)d_in[0];
    const float* y   = (const float*)d_in[1];
    const int*   ei  = (const int*)d_in[2];
    const float* Wg1 = (const float*)d_in[3];
    const float* bg1 = (const float*)d_in[4];
    const float* Wg2 = (const float*)d_in[5];
    const float* bg2 = (const float*)d_in[6];
    const float* Wl  = (const float*)d_in[7];
    const float* bl  = (const float*)d_in[8];
    const float* Wf  = (const float*)d_in[9];
    const float* bf  = (const float*)d_in[10];
    float* out = (float*)d_out;

    int n = in_sizes[0] / 128;
    int e = in_sizes[2] / 2;
    const int* src = ei;
    const int* dst = ei + e;

    float *bufA, *bufB, *h2;
    cudaGetSymbolAddress((void**)&bufA, g_bufA);
    cudaGetSymbolAddress((void**)&bufB, g_bufB);
    cudaGetSymbolAddress((void**)&h2, g_h2);

    size_t smem64  = (size_t)(64 * BN + BM * KCP) * 4;
    size_t smem128 = (size_t)(128 * BN + BM * KCP) * 4;
    size_t smem192 = (size_t)(192 * BN + BM * KCP) * 4;
    cudaFuncSetAttribute((const void*)gemm_kernel<64, 64, 64, 0>,
                         cudaFuncAttributeMaxDynamicSharedMemorySize, (int)smem64);
    cudaFuncSetAttribute((const void*)gemm_kernel<128, 128, 128, 0>,
                         cudaFuncAttributeMaxDynamicSharedMemorySize, (int)smem128);
    cudaFuncSetAttribute((const void*)gemm_kernel<192, 64, 128, 1>,
                         cudaFuncAttributeMaxDynamicSharedMemorySize, (int)smem192);

    int nb_n = (n + 255) / 256;
    int nb_e = (e + 255) / 256;
    int nb_scan = (n + 1023) / 1024;

    // CSR + dinv
    zero_counts_kernel<<<nb_n, 256>>>(n);
    count_edges_kernel<<<nb_e, 256>>>(dst, e);
    scan1_kernel<<<nb_scan, 1024>>>(n);
    scan2_kernel<<<1, 128>>>(nb_scan);
    scan3_kernel<<<(n + 1024) / 1024 + 1, 1024>>>(n, nb_scan);
    scatter_edges_kernel<<<nb_e, 256>>>(src, dst, e);

    int rb = (n + BM - 1) / BM;
    dim3 g128(rb, 2);   // C=128 -> two column tiles
    dim3 g64(rb, 1);
    int agg128_blocks = (int)(((size_t)n * 32 + 255) / 256);
    int agg64_blocks  = (int)(((size_t)n * 16 + 255) / 256);

    // feature branch
    gemm_kernel<128, 128, 128, 0><<<g128, 128, smem128>>>(x, nullptr, Wg1, nullptr, bufA, n);
    agg_kernel<128, true><<<agg128_blocks, 256>>>(bufA, bg1, bufB, n);
    gemm_kernel<128, 128, 128, 0><<<g128, 128, smem128>>>(bufB, nullptr, Wg2, nullptr, bufA, n);
    agg_kernel<128, false><<<agg128_blocks, 256>>>(bufA, bg2, h2, n);

    // label branch (10 layers, relu except last); result ends in bufB
    gemm_kernel<64, 64, 64, 0><<<g64, 128, smem64>>>(y, nullptr, Wl, nullptr, bufA, n);
    agg_kernel<64, true><<<agg64_blocks, 256>>>(bufA, bl, bufB, n);
    for (int j = 1; j < 10; j++) {
        gemm_kernel<64, 64, 64, 0><<<g64, 128, smem64>>>(
            bufB, nullptr, Wl + (size_t)j * 64 * 64, nullptr, bufA, n);
        if (j < 9)
            agg_kernel<64, true><<<agg64_blocks, 256>>>(bufA, bl + (size_t)j * 64, bufB, n);
        else
            agg_kernel<64, false><<<agg64_blocks, 256>>>(bufA, bl + (size_t)j * 64, bufB, n);
    }

    // final fused layer: sigmoid(concat(h2, xl) @ Wf + bf)
    gemm_kernel<192, 64, 128, 1><<<g64, 128, smem192>>>(h2, bufB, Wf, bf, out, n);
}

// round 3
// speedup vs baseline: 2.0051x; 1.6921x over previous
#include <cuda_runtime.h>
#include <cuda_fp16.h>
#include <mma.h>
#include <math.h>

using namespace nvcuda;

#define NMAX 100000
#define EMAX 1600000

// ---------------- device scratch ----------------
__device__ float  g_dinv[NMAX];
__device__ int    g_cnt[NMAX];
__device__ int    g_fill[NMAX];
__device__ int    g_rowptr[NMAX + 1];
__device__ int    g_bsum[256];
__device__ int    g_col[EMAX];
__device__ __half g_hA[(size_t)NMAX * 128];
__device__ __half g_hB[(size_t)NMAX * 128];
__device__ __half g_hH2[(size_t)NMAX * 128];

// ---------------- CSR build ----------------
__global__ void zero_counts_kernel(int n) {
    int i = blockIdx.x * blockDim.x + threadIdx.x;
    if (i < n) { g_cnt[i] = 0; g_fill[i] = 0; }
}

__global__ void count_edges_kernel(const int* __restrict__ dst, int e) {
    int i = blockIdx.x * blockDim.x + threadIdx.x;
    if (i < e) atomicAdd(&g_cnt[dst[i]], 1);
}

__global__ void scan1_kernel(int n) {
    __shared__ int s[1024];
    int tid = threadIdx.x;
    int i = blockIdx.x * 1024 + tid;
    int v = (i < n) ? g_cnt[i] : 0;
    s[tid] = v;
    __syncthreads();
    for (int off = 1; off < 1024; off <<= 1) {
        int t2 = (tid >= off) ? s[tid - off] : 0;
        __syncthreads();
        s[tid] += t2;
        __syncthreads();
    }
    if (i < n) {
        g_rowptr[i] = s[tid] - v;
        g_dinv[i] = rsqrtf((float)(v + 1));
    }
    if (tid == 1023) g_bsum[blockIdx.x] = s[1023];
}

__global__ void scan2_kernel(int nb) {
    __shared__ int s[128];
    int tid = threadIdx.x;
    int v = (tid < nb) ? g_bsum[tid] : 0;
    s[tid] = v;
    __syncthreads();
    for (int off = 1; off < 128; off <<= 1) {
        int t2 = (tid >= off) ? s[tid - off] : 0;
        __syncthreads();
        s[tid] += t2;
        __syncthreads();
    }
    if (tid < nb) g_bsum[tid] = s[tid] - v;
    if (tid == 127) g_bsum[nb] = s[127];
}

__global__ void scan3_kernel(int n, int nb) {
    int i = blockIdx.x * blockDim.x + threadIdx.x;
    if (i < n) g_rowptr[i] += g_bsum[i >> 10];
    if (i == 0) g_rowptr[n] = g_bsum[nb];
}

__global__ void scatter_edges_kernel(const int* __restrict__ src,
                                     const int* __restrict__ dst, int e) {
    int i = blockIdx.x * blockDim.x + threadIdx.x;
    if (i < e) {
        int d = dst[i];
        int p = g_rowptr[d] + atomicAdd(&g_fill[d], 1);
        g_col[p] = src[i];
    }
}

// ---------------- wmma GEMM ----------------
// out tile [BM=128 rows] x [BN=64 cols].  4 warps, each warp: 32 rows x 64 cols.
// A source: rows from A1 (TA elements, width K1) for k<K1, A2 (half, width K-K1)
// for k>=K1.  EPI 0: A rows pre-scaled by dinv, output half.
// EPI 1: output = sigmoid(acc + bias), fp32.
#define GBM 128
#define GBN 64

template <int K, int C, int K1, int EPI, typename TA>
__global__ __launch_bounds__(128) void gemm_wmma_kernel(
    const TA* __restrict__ A1, const __half* __restrict__ A2,
    const float* __restrict__ W, const float* __restrict__ bias,
    void* __restrict__ outv, int n) {
    constexpr int LDW = GBN + 8;   // half
    constexpr int LDA = K + 8;     // half
    constexpr int LDS_ = GBN + 4;  // float staging
    extern __shared__ char smraw[];
    __half* Ws = (__half*)smraw;
    __half* As = (__half*)(smraw + (size_t)K * LDW * 2);
    float*  St = (float*)(smraw + (size_t)K * LDW * 2);

    const int t = threadIdx.x;
    const int w = t >> 5;
    const int row0 = blockIdx.x * GBM;
    const int bn0 = blockIdx.y * GBN;

    // load W tile [K][BN] fp32 -> half
    for (int idx = t; idx < K * GBN / 4; idx += 128) {
        int k = idx / (GBN / 4);
        int j = (idx % (GBN / 4)) * 4;
        const float* src = W + (size_t)k * C + bn0 + j;
        Ws[k * LDW + j + 0] = __float2half(src[0]);
        Ws[k * LDW + j + 1] = __float2half(src[1]);
        Ws[k * LDW + j + 2] = __float2half(src[2]);
        Ws[k * LDW + j + 3] = __float2half(src[3]);
    }

    // load A tile [BM][K] (pre-scaled by dinv when EPI==0)
    constexpr int CPR = K / 8;  // 8-elem chunks per row
#pragma unroll
    for (int it = 0; it < GBM * CPR / 128; it++) {
        int cidx = t + it * 128;
        int r = cidx / CPR;
        int kq = (cidx % CPR) * 8;
        int gr = row0 + r;
        float vals[8];
        if (gr < n) {
            float s = (EPI == 0) ? g_dinv[gr] : 1.0f;
            if (kq < K1) {
                const TA* p = A1 + (size_t)gr * K1 + kq;
#pragma unroll
                for (int q = 0; q < 8; q++) vals[q] = s * (float)p[q];
            } else {
                const __half* p = A2 + (size_t)gr * (K - K1) + (kq - K1);
#pragma unroll
                for (int q = 0; q < 8; q++) vals[q] = s * __half2float(p[q]);
            }
        } else {
#pragma unroll
            for (int q = 0; q < 8; q++) vals[q] = 0.f;
        }
        __half* dstp = As + r * LDA + kq;
#pragma unroll
        for (int q = 0; q < 8; q++) dstp[q] = __float2half(vals[q]);
    }
    __syncthreads();

    wmma::fragment<wmma::accumulator, 16, 16, 16, float> acc[2][4];
#pragma unroll
    for (int i = 0; i < 2; i++)
#pragma unroll
        for (int j = 0; j < 4; j++) wmma::fill_fragment(acc[i][j], 0.f);

    for (int k = 0; k < K; k += 16) {
        wmma::fragment<wmma::matrix_a, 16, 16, 16, __half, wmma::row_major> af[2];
        wmma::fragment<wmma::matrix_b, 16, 16, 16, __half, wmma::row_major> bfr[4];
        wmma::load_matrix_sync(af[0], As + (w * 32 + 0) * LDA + k, LDA);
        wmma::load_matrix_sync(af[1], As + (w * 32 + 16) * LDA + k, LDA);
#pragma unroll
        for (int j = 0; j < 4; j++)
            wmma::load_matrix_sync(bfr[j], Ws + k * LDW + j * 16, LDW);
#pragma unroll
        for (int i = 0; i < 2; i++)
#pragma unroll
            for (int j = 0; j < 4; j++)
                wmma::mma_sync(acc[i][j], af[i], bfr[j], acc[i][j]);
    }

    __syncthreads();  // done reading As; staging aliases it
#pragma unroll
    for (int i = 0; i < 2; i++)
#pragma unroll
        for (int j = 0; j < 4; j++)
            wmma::store_matrix_sync(St + (w * 32 + i * 16) * LDS_ + j * 16,
                                    acc[i][j], LDS_, wmma::mem_row_major);
    __syncthreads();

    // epilogue: 128 threads = 16 rows x 8 lanes, 8 row-groups
    const int lane = t & 7;
    const int rsub = t >> 3;
#pragma unroll
    for (int g = 0; g < 8; g++) {
        int r = g * 16 + rsub;
        int gr = row0 + r;
        if (gr >= n) continue;
        const float* sp = St + r * LDS_ + lane * 8;
        if (EPI == 0) {
            __half* outp = (__half*)outv + (size_t)gr * C + bn0 + lane * 8;
            __half hv[8];
#pragma unroll
            for (int q = 0; q < 8; q++) hv[q] = __float2half(sp[q]);
            *(uint4*)outp = *(uint4*)hv;
        } else {
            float* outp = (float*)outv + (size_t)gr * C + bn0 + lane * 8;
            const float* bp = bias + bn0 + lane * 8;
            float ov[8];
#pragma unroll
            for (int q = 0; q < 8; q++)
                ov[q] = 1.f / (1.f + __expf(-(sp[q] + bp[q])));
            *(float4*)outp = *(float4*)ov;
            *(float4*)(outp + 4) = *(float4*)(ov + 4);
        }
    }
}

// ---------------- aggregation (half msgs, fp32 accumulate) ----------------
// out[v] = relu?(dinv[v]*(sum_nbr hs[u] + hs[v]) + b), stored as half
template <int D, bool RELU>
__global__ __launch_bounds__(256) void agg_kernel(
    const __half* __restrict__ hs, const float* __restrict__ bias,
    __half* __restrict__ out, int n) {
    constexpr int LPN = D / 8;  // lanes per node, 8 halfs each
    int idx = blockIdx.x * blockDim.x + threadIdx.x;
    int v = idx / LPN;
    int lane = idx % LPN;
    if (v >= n) return;
    int c = lane * 8;
    const uint4* base = (const uint4*)hs;
    size_t selfidx = ((size_t)v * D + c) >> 3;

    float acc[8];
    {
        uint4 sv = base[selfidx];
        const __half2* h = (const __half2*)&sv;
#pragma unroll
        for (int q = 0; q < 4; q++) {
            float2 f = __half22float2(h[q]);
            acc[2 * q] = f.x; acc[2 * q + 1] = f.y;
        }
    }
    int beg = g_rowptr[v], end = g_rowptr[v + 1];
    int e = beg;
    for (; e + 1 < end; e += 2) {
        int u0 = g_col[e], u1 = g_col[e + 1];
        uint4 m0 = base[((size_t)u0 * D + c) >> 3];
        uint4 m1 = base[((size_t)u1 * D + c) >> 3];
        const __half2* h0 = (const __half2*)&m0;
        const __half2* h1 = (const __half2*)&m1;
#pragma unroll
        for (int q = 0; q < 4; q++) {
            float2 f0 = __half22float2(h0[q]);
            float2 f1 = __half22float2(h1[q]);
            acc[2 * q] += f0.x + f1.x;
            acc[2 * q + 1] += f0.y + f1.y;
        }
    }
    if (e < end) {
        int u = g_col[e];
        uint4 m = base[((size_t)u * D + c) >> 3];
        const __half2* h = (const __half2*)&m;
#pragma unroll
        for (int q = 0; q < 4; q++) {
            float2 f = __half22float2(h[q]);
            acc[2 * q] += f.x;
            acc[2 * q + 1] += f.y;
        }
    }
    float s = g_dinv[v];
    float4 b0 = *(const float4*)(bias + c);
    float4 b1 = *(const float4*)(bias + c + 4);
    float bb[8] = {b0.x, b0.y, b0.z, b0.w, b1.x, b1.y, b1.z, b1.w};
    __half hv[8];
#pragma unroll
    for (int q = 0; q < 8; q++) {
        float r = s * acc[q] + bb[q];
        if (RELU) r = fmaxf(r, 0.f);
        hv[q] = __float2half(r);
    }
    ((uint4*)out)[selfidx] = *(uint4*)hv;
}

// ---------------- host launch ----------------
extern "C" void kernel_launch(void* const* d_in, const int* in_sizes, int n_in,
                              void* d_out, int out_size) {
    const float* x   = (const float*)d_in[0];
    const float* y   = (const float*)d_in[1];
    const int*   ei  = (const int*)d_in[2];
    const float* Wg1 = (const float*)d_in[3];
    const float* bg1 = (const float*)d_in[4];
    const float* Wg2 = (const float*)d_in[5];
    const float* bg2 = (const float*)d_in[6];
    const float* Wl  = (const float*)d_in[7];
    const float* bl  = (const float*)d_in[8];
    const float* Wf  = (const float*)d_in[9];
    const float* bf  = (const float*)d_in[10];
    float* out = (float*)d_out;

    int n = in_sizes[0] / 128;
    int e = in_sizes[2] / 2;
    const int* src = ei;
    const int* dst = ei + e;

    __half *hA, *hB, *hH2;
    cudaGetSymbolAddress((void**)&hA, g_hA);
    cudaGetSymbolAddress((void**)&hB, g_hB);
    cudaGetSymbolAddress((void**)&hH2, g_hH2);

    auto smem_sz = [](int K) -> size_t {
        size_t WsB = (size_t)K * (GBN + 8) * 2;
        size_t AsB = (size_t)GBM * (K + 8) * 2;
        size_t StB = (size_t)GBM * (GBN + 4) * 4;
        return WsB + (AsB > StB ? AsB : StB);
    };
    size_t sm64 = smem_sz(64), sm128 = smem_sz(128), sm192 = smem_sz(192);

    cudaFuncSetAttribute((const void*)gemm_wmma_kernel<128, 128, 128, 0, float>,
                         cudaFuncAttributeMaxDynamicSharedMemorySize, (int)sm128);
    cudaFuncSetAttribute((const void*)gemm_wmma_kernel<128, 128, 128, 0, __half>,
                         cudaFuncAttributeMaxDynamicSharedMemorySize, (int)sm128);
    cudaFuncSetAttribute((const void*)gemm_wmma_kernel<64, 64, 64, 0, float>,
                         cudaFuncAttributeMaxDynamicSharedMemorySize, (int)sm64);
    cudaFuncSetAttribute((const void*)gemm_wmma_kernel<64, 64, 64, 0, __half>,
                         cudaFuncAttributeMaxDynamicSharedMemorySize, (int)sm64);
    cudaFuncSetAttribute((const void*)gemm_wmma_kernel<192, 64, 128, 1, __half>,
                         cudaFuncAttributeMaxDynamicSharedMemorySize, (int)sm192);

    int nb_n = (n + 255) / 256;
    int nb_e = (e + 255) / 256;
    int nb_scan = (n + 1023) / 1024;

    // CSR + dinv
    zero_counts_kernel<<<nb_n, 256>>>(n);
    count_edges_kernel<<<nb_e, 256>>>(dst, e);
    scan1_kernel<<<nb_scan, 1024>>>(n);
    scan2_kernel<<<1, 128>>>(nb_scan);
    scan3_kernel<<<(n + 1024) / 1024 + 1, 1024>>>(n, nb_scan);
    scatter_edges_kernel<<<nb_e, 256>>>(src, dst, e);

    int rb = (n + GBM - 1) / GBM;
    dim3 g128(rb, 2);
    dim3 g64(rb, 1);
    int agg128_blocks = (int)(((size_t)n * 16 + 255) / 256);
    int agg64_blocks  = (int)(((size_t)n * 8 + 255) / 256);

    // feature branch
    gemm_wmma_kernel<128, 128, 128, 0, float><<<g128, 128, sm128>>>(
        x, nullptr, Wg1, nullptr, hA, n);
    agg_kernel<128, true><<<agg128_blocks, 256>>>(hA, bg1, hB, n);
    gemm_wmma_kernel<128, 128, 128, 0, __half><<<g128, 128, sm128>>>(
        hB, nullptr, Wg2, nullptr, hA, n);
    agg_kernel<128, false><<<agg128_blocks, 256>>>(hA, bg2, hH2, n);

    // label branch
    gemm_wmma_kernel<64, 64, 64, 0, float><<<g64, 128, sm64>>>(
        y, nullptr, Wl, nullptr, hA, n);
    agg_kernel<64, true><<<agg64_blocks, 256>>>(hA, bl, hB, n);
    for (int j = 1; j < 10; j++) {
        gemm_wmma_kernel<64, 64, 64, 0, __half><<<g64, 128, sm64>>>(
            hB, nullptr, Wl + (size_t)j * 64 * 64, nullptr, hA, n);
        if (j < 9)
            agg_kernel<64, true><<<agg64_blocks, 256>>>(hA, bl + (size_t)j * 64, hB, n);
        else
            agg_kernel<64, false><<<agg64_blocks, 256>>>(hA, bl + (size_t)j * 64, hB, n);
    }

    // final fused layer: sigmoid(concat(h2, xl) @ Wf + bf)
    gemm_wmma_kernel<192, 64, 128, 1, __half><<<g64, 128, sm192>>>(
        hH2, hB, Wf, bf, out, n);
}